// round 2
// baseline (speedup 1.0000x reference)
#include <cuda_runtime.h>
#include <cuda_bf16.h>
#include <stdint.h>

#define KCLS   64
#define QPC    128
#define DIMK   1024
#define NROWS  (KCLS * QPC)     // 8192
#define TM     64               // rows per CTA
#define KC     32               // k-chunk
#define NCHUNK (DIMK / KC)      // 32
#define SA_STR 40               // bf16 elems per smem row (KC + 8 pad) -> conflict-free frag LDS
#define SL_STR 65               // fp32 elems per logits row

__device__ float g_p2[3][KCLS];
__device__ float g_rvar[3][KCLS];
__device__ float g_loss_sum;
__device__ int   g_acc_cnt;

// ---------------------------------------------------------------------------
// prep: per-proto squared norms, reciprocal variances, zero global accumulators
// ---------------------------------------------------------------------------
__global__ void prep_kernel(const float* __restrict__ pTF, const float* __restrict__ vTF,
                            const float* __restrict__ pDE, const float* __restrict__ vDE,
                            const float* __restrict__ pFFT, const float* __restrict__ vFFT)
{
    if (blockIdx.x == 0 && threadIdx.x == 0) { g_loss_sum = 0.0f; g_acc_cnt = 0; }
    int gw   = (blockIdx.x * blockDim.x + threadIdx.x) >> 5;
    int lane = threadIdx.x & 31;
    int nw   = (gridDim.x * blockDim.x) >> 5;
    for (int task = gw; task < 3 * KCLS; task += nw) {
        int m = task / KCLS;
        int j = task - m * KCLS;
        const float* p = (m == 0 ? pTF : (m == 1 ? pDE : pFFT)) + (size_t)j * DIMK;
        float s = 0.0f;
        for (int c = lane * 4; c < DIMK; c += 128) {
            float4 v = *reinterpret_cast<const float4*>(p + c);
            s += v.x * v.x + v.y * v.y + v.z * v.z + v.w * v.w;
        }
        #pragma unroll
        for (int o = 16; o > 0; o >>= 1) s += __shfl_xor_sync(0xffffffffu, s, o);
        if (lane == 0) {
            g_p2[m][j] = s;
            const float* v = (m == 0 ? vTF : (m == 1 ? vDE : vFFT));
            g_rvar[m][j] = 1.0f / v[j];
        }
    }
}

// ---------------------------------------------------------------------------
// bf16 split helpers + mma
// ---------------------------------------------------------------------------
__device__ __forceinline__ void split8(__nv_bfloat16* hi, __nv_bfloat16* lo,
                                       float4 a, float4 b)
{
    float f[8] = {a.x, a.y, a.z, a.w, b.x, b.y, b.z, b.w};
    uint32_t hw[4], lw[4];
    #pragma unroll
    for (int i = 0; i < 4; i++) {
        __nv_bfloat162 h = __floats2bfloat162_rn(f[2*i], f[2*i+1]);
        float r0 = f[2*i]     - __bfloat162float(h.x);
        float r1 = f[2*i + 1] - __bfloat162float(h.y);
        __nv_bfloat162 l = __floats2bfloat162_rn(r0, r1);
        hw[i] = *reinterpret_cast<uint32_t*>(&h);
        lw[i] = *reinterpret_cast<uint32_t*>(&l);
    }
    *reinterpret_cast<uint4*>(hi) = make_uint4(hw[0], hw[1], hw[2], hw[3]);
    *reinterpret_cast<uint4*>(lo) = make_uint4(lw[0], lw[1], lw[2], lw[3]);
}

__device__ __forceinline__ void mma_bf16(float c[4], const uint32_t a[4], const uint32_t b[2])
{
    asm volatile(
        "mma.sync.aligned.m16n8k16.row.col.f32.bf16.bf16.f32 "
        "{%0,%1,%2,%3}, {%4,%5,%6,%7}, {%8,%9}, {%0,%1,%2,%3};\n"
        : "+f"(c[0]), "+f"(c[1]), "+f"(c[2]), "+f"(c[3])
        : "r"(a[0]), "r"(a[1]), "r"(a[2]), "r"(a[3]), "r"(b[0]), "r"(b[1]));
}

// ---------------------------------------------------------------------------
// fused main kernel: GEMM (bf16 hi/lo split MMA) + softmax + loss + argmax
// ---------------------------------------------------------------------------
__global__ __launch_bounds__(256)
void fusion_kernel(const float* __restrict__ xTF, const float* __restrict__ xDE,
                   const float* __restrict__ xFFT,
                   const float* __restrict__ pTF, const float* __restrict__ pDE,
                   const float* __restrict__ pFFT)
{
    // A/B split tiles; the same buffer is reused as the logits tile (sL) in the epilogue
    __shared__ __align__(16) unsigned char s_ab[4 * TM * SA_STR * 2];   // 20480 B >= 64*65*4
    __shared__ float sPred[TM * KCLS];                                  // persists across modalities
    __shared__ float sX2[TM];
    __shared__ float sP2[KCLS];
    __shared__ float sRv[KCLS];
    __shared__ float sLossRow[TM];
    __shared__ float sBLoss;
    __shared__ int   sBAcc;

    __nv_bfloat16* Ah = reinterpret_cast<__nv_bfloat16*>(s_ab);
    __nv_bfloat16* Al = Ah + TM * SA_STR;
    __nv_bfloat16* Bh = Al + TM * SA_STR;
    __nv_bfloat16* Bl = Bh + KCLS * SA_STR;
    float* sL = reinterpret_cast<float*>(s_ab);

    const int tid  = threadIdx.x;
    const int row  = tid >> 2;          // 0..63 : row for load/softmax duty
    const int sub  = tid & 3;           // 4 threads per row
    const int lane = tid & 31;
    const int warp = tid >> 5;
    const int wm   = warp >> 2;         // warp grid 2x4 over 64x64 output
    const int wn   = warp & 3;
    const int gr   = lane >> 2;
    const int lk   = (lane & 3) << 1;

    for (int i = tid; i < TM * KCLS; i += 256) sPred[i] = 0.0f;
    if (tid < TM) sLossRow[tid] = 0.0f;
    if (tid == 0) { sBLoss = 0.0f; sBAcc = 0; }

    const float* xs[3]  = {xTF, xDE, xFFT};
    const float* ps[3]  = {pTF, pDE, pFFT};
    const float  wts[3] = {1.0f, 0.8f, 0.6f};

    const size_t growbase = (size_t)blockIdx.x * TM;
    const int y_row = (int)((growbase + row) >> 7);   // class label for this row

    for (int m = 0; m < 3; m++) {
        const float* xrow = xs[m] + (growbase + row) * DIMK + sub * 8;
        const float* prow = ps[m] + (size_t)row * DIMK + sub * 8;   // proto index == row
        if (tid < KCLS) { sP2[tid] = g_p2[m][tid]; sRv[tid] = g_rvar[m][tid]; }

        float acc[2][2][4] = {};
        float x2p = 0.0f;

        // register-prefetch pipeline over K chunks
        float4 a0 = *reinterpret_cast<const float4*>(xrow);
        float4 a1 = *reinterpret_cast<const float4*>(xrow + 4);
        float4 b0 = *reinterpret_cast<const float4*>(prow);
        float4 b1 = *reinterpret_cast<const float4*>(prow + 4);

        for (int ci = 0; ci < NCHUNK; ci++) {
            __syncthreads();   // previous chunk's MMA reads (or epilogue reads) done
            x2p += a0.x*a0.x + a0.y*a0.y + a0.z*a0.z + a0.w*a0.w
                 + a1.x*a1.x + a1.y*a1.y + a1.z*a1.z + a1.w*a1.w;
            split8(Ah + row * SA_STR + sub * 8, Al + row * SA_STR + sub * 8, a0, a1);
            split8(Bh + row * SA_STR + sub * 8, Bl + row * SA_STR + sub * 8, b0, b1);

            // prefetch next chunk (clamped; last iteration re-reads harmlessly)
            const int cn = (ci + 1 < NCHUNK) ? (ci + 1) : ci;
            float4 na0 = *reinterpret_cast<const float4*>(xrow + cn * KC);
            float4 na1 = *reinterpret_cast<const float4*>(xrow + cn * KC + 4);
            float4 nb0 = *reinterpret_cast<const float4*>(prow + cn * KC);
            float4 nb1 = *reinterpret_cast<const float4*>(prow + cn * KC + 4);

            __syncthreads();   // tiles visible

            #pragma unroll
            for (int kk = 0; kk < KC / 16; kk++) {
                const int kb = kk * 16 + lk;
                uint32_t ah[2][4], alr[2][4];
                #pragma unroll
                for (int mt = 0; mt < 2; mt++) {
                    const int r0 = (wm * 32 + mt * 16 + gr) * SA_STR + kb;
                    const int r1 = r0 + 8 * SA_STR;
                    ah[mt][0]  = *reinterpret_cast<const uint32_t*>(Ah + r0);
                    ah[mt][1]  = *reinterpret_cast<const uint32_t*>(Ah + r1);
                    ah[mt][2]  = *reinterpret_cast<const uint32_t*>(Ah + r0 + 8);
                    ah[mt][3]  = *reinterpret_cast<const uint32_t*>(Ah + r1 + 8);
                    alr[mt][0] = *reinterpret_cast<const uint32_t*>(Al + r0);
                    alr[mt][1] = *reinterpret_cast<const uint32_t*>(Al + r1);
                    alr[mt][2] = *reinterpret_cast<const uint32_t*>(Al + r0 + 8);
                    alr[mt][3] = *reinterpret_cast<const uint32_t*>(Al + r1 + 8);
                }
                uint32_t bh[2][2], blr[2][2];
                #pragma unroll
                for (int nt = 0; nt < 2; nt++) {
                    const int n0 = (wn * 16 + nt * 8 + gr) * SA_STR + kb;
                    bh[nt][0]  = *reinterpret_cast<const uint32_t*>(Bh + n0);
                    bh[nt][1]  = *reinterpret_cast<const uint32_t*>(Bh + n0 + 8);
                    blr[nt][0] = *reinterpret_cast<const uint32_t*>(Bl + n0);
                    blr[nt][1] = *reinterpret_cast<const uint32_t*>(Bl + n0 + 8);
                }
                #pragma unroll
                for (int mt = 0; mt < 2; mt++)
                    #pragma unroll
                    for (int nt = 0; nt < 2; nt++) {
                        mma_bf16(acc[mt][nt], ah[mt],  bh[nt]);   // hi*hi
                        mma_bf16(acc[mt][nt], ah[mt],  blr[nt]);  // hi*lo
                        mma_bf16(acc[mt][nt], alr[mt], bh[nt]);   // lo*hi
                    }
            }
            a0 = na0; a1 = na1; b0 = nb0; b1 = nb1;
        }

        // row squared norms
        x2p += __shfl_xor_sync(0xffffffffu, x2p, 1);
        x2p += __shfl_xor_sync(0xffffffffu, x2p, 2);
        if (sub == 0) sX2[row] = x2p;
        __syncthreads();

        // logits L = (2*xp - x2 - p2) / var  into reused smem
        #pragma unroll
        for (int mt = 0; mt < 2; mt++) {
            const int r0 = wm * 32 + mt * 16 + gr;
            const float x2a = sX2[r0], x2b = sX2[r0 + 8];
            #pragma unroll
            for (int nt = 0; nt < 2; nt++) {
                const int c0 = wn * 16 + nt * 8 + lk;
                sL[r0 * SL_STR + c0]           = (2.0f * acc[mt][nt][0] - x2a - sP2[c0])     * sRv[c0];
                sL[r0 * SL_STR + c0 + 1]       = (2.0f * acc[mt][nt][1] - x2a - sP2[c0 + 1]) * sRv[c0 + 1];
                sL[(r0 + 8) * SL_STR + c0]     = (2.0f * acc[mt][nt][2] - x2b - sP2[c0])     * sRv[c0];
                sL[(r0 + 8) * SL_STR + c0 + 1] = (2.0f * acc[mt][nt][3] - x2b - sP2[c0 + 1]) * sRv[c0 + 1];
            }
        }
        __syncthreads();

        // softmax per row, 4 threads/row, stripes j = sub + 4t
        const float* Lr = sL + row * SL_STR;
        float mx = -3.4e38f;
        #pragma unroll
        for (int t = 0; t < 16; t++) mx = fmaxf(mx, Lr[sub + 4 * t]);
        mx = fmaxf(mx, __shfl_xor_sync(0xffffffffu, mx, 1));
        mx = fmaxf(mx, __shfl_xor_sync(0xffffffffu, mx, 2));

        float ex[16];
        float sden = 0.0f;
        #pragma unroll
        for (int t = 0; t < 16; t++) { ex[t] = __expf(Lr[sub + 4 * t] - mx); sden += ex[t]; }
        sden += __shfl_xor_sync(0xffffffffu, sden, 1);
        sden += __shfl_xor_sync(0xffffffffu, sden, 2);

        const float scale = wts[m] / sden;
        #pragma unroll
        for (int t = 0; t < 16; t++) sPred[row * KCLS + sub + 4 * t] += ex[t] * scale;

        if ((y_row & 3) == sub)
            sLossRow[row] += -wts[m] * (Lr[y_row] - mx - logf(sden));
        __syncthreads();
    }

    // argmax over fused preds (first-max tie-break like jnp.argmax)
    float bv = -3.4e38f; int bi = 0;
    #pragma unroll
    for (int t = 0; t < 16; t++) {
        const int j = sub + 4 * t;
        const float v = sPred[row * KCLS + j];
        if (v > bv) { bv = v; bi = j; }
    }
    #pragma unroll
    for (int o = 1; o <= 2; o <<= 1) {
        const float ov = __shfl_xor_sync(0xffffffffu, bv, o);
        const int   oi = __shfl_xor_sync(0xffffffffu, bi, o);
        if (ov > bv || (ov == bv && oi < bi)) { bv = ov; bi = oi; }
    }
    if (sub == 0) {
        atomicAdd(&sBLoss, sLossRow[row]);
        if (bi == y_row) atomicAdd(&sBAcc, 1);
    }
    __syncthreads();
    if (tid == 0) {
        atomicAdd(&g_loss_sum, sBLoss);
        atomicAdd(&g_acc_cnt, sBAcc);
    }
}

// ---------------------------------------------------------------------------
__global__ void finalize_kernel(float* __restrict__ out, int n)
{
    const float loss = g_loss_sum * (1.0f / NROWS);
    const float acc  = (float)g_acc_cnt * (1.0f / NROWS);
    for (int i = threadIdx.x; i < n; i += blockDim.x)
        out[i] = (i == 0) ? loss : (i == 1 ? acc : 0.0f);
}

// ---------------------------------------------------------------------------
extern "C" void kernel_launch(void* const* d_in, const int* in_sizes, int n_in,
                              void* d_out, int out_size)
{
    (void)in_sizes; (void)n_in;
    const float* TFq  = (const float*)d_in[0];
    const float* pTF  = (const float*)d_in[1];
    const float* vTF  = (const float*)d_in[2];
    const float* DEq  = (const float*)d_in[3];
    const float* pDE  = (const float*)d_in[4];
    const float* vDE  = (const float*)d_in[5];
    const float* FFTq = (const float*)d_in[6];
    const float* pFFT = (const float*)d_in[7];
    const float* vFFT = (const float*)d_in[8];

    prep_kernel<<<6, 256>>>(pTF, vTF, pDE, vDE, pFFT, vFFT);
    fusion_kernel<<<NROWS / TM, 256>>>(TFq, DEq, FFTq, pTF, pDE, pFFT);
    finalize_kernel<<<1, 64>>>((float*)d_out, out_size);
}

// round 7
// speedup vs baseline: 1.2836x; 1.2836x over previous
#include <cuda_runtime.h>
#include <cuda_bf16.h>
#include <stdint.h>

#define KCLS   64
#define QPC    128
#define DIMK   1024
#define NROWS  (KCLS * QPC)      // 8192
#define TMR    32                // rows per CTA
#define NCTA   (NROWS / TMR)     // 256
#define KC     64                // k elems per chunk
#define NCHUNK (DIMK / KC)       // 16

// ---------------- smem layout (bytes), stride-72 bf16 rows (144B) ------------
#define A_STR   72
#define OFF_AH  0
#define OFF_AL  4608                     // 32*72*2
#define OFF_BH  9216
#define OFF_BL  18432                    // + 64*72*2
#define BUFSZ   27648
#define OFF_SL  (2 * BUFSZ)              // 55296, logits 32 x 72 fp32
#define SL_STR  72
#define OFF_SX2 (OFF_SL + 32 * SL_STR * 4)   // 64512
#define OFF_SP2 (OFF_SX2 + 128)
#define OFF_SRV (OFF_SP2 + 256)
#define OFF_RED (OFF_SRV + 256)          // sBLoss (f32), sBAcc (int)
#define SMEM_TOTAL (OFF_RED + 16)        // 65168 -> 2 CTAs/SM

__device__ float g_p2[3][KCLS];
__device__ float g_rvar[3][KCLS];
__device__ float g_loss_sum;
__device__ int   g_acc_cnt;
// pre-split proto tiles: [m][chunk][proto][64] bf16 (unpadded, L2-resident)
__device__ __nv_bfloat16 g_Bh[3 * NCHUNK * KCLS * KC];
__device__ __nv_bfloat16 g_Bl[3 * NCHUNK * KCLS * KC];

// ---------------------------------------------------------------------------
__device__ __forceinline__ uint32_t smem_u32(const void* p) {
    uint32_t a;
    asm("{ .reg .u64 t; cvta.to.shared.u64 t, %1; cvt.u32.u64 %0, t; }" : "=r"(a) : "l"(p));
    return a;
}

__device__ __forceinline__ void ldsm4(uint32_t* r, uint32_t a) {
    asm volatile("ldmatrix.sync.aligned.m8n8.x4.shared.b16 {%0,%1,%2,%3}, [%4];"
                 : "=r"(r[0]), "=r"(r[1]), "=r"(r[2]), "=r"(r[3]) : "r"(a));
}
__device__ __forceinline__ void ldsm2(uint32_t* r, uint32_t a) {
    asm volatile("ldmatrix.sync.aligned.m8n8.x2.shared.b16 {%0,%1}, [%2];"
                 : "=r"(r[0]), "=r"(r[1]) : "r"(a));
}
__device__ __forceinline__ void mma_bf16(float c[4], const uint32_t a[4], const uint32_t b[2]) {
    asm volatile(
        "mma.sync.aligned.m16n8k16.row.col.f32.bf16.bf16.f32 "
        "{%0,%1,%2,%3}, {%4,%5,%6,%7}, {%8,%9}, {%0,%1,%2,%3};\n"
        : "+f"(c[0]), "+f"(c[1]), "+f"(c[2]), "+f"(c[3])
        : "r"(a[0]), "r"(a[1]), "r"(a[2]), "r"(a[3]), "r"(b[0]), "r"(b[1]));
}

// fp32x8 -> bf16 hi + bf16 lo
__device__ __forceinline__ void split8(float4 a, float4 b, uint4& hi, uint4& lo) {
    float f[8] = {a.x, a.y, a.z, a.w, b.x, b.y, b.z, b.w};
    uint32_t hw[4], lw[4];
    #pragma unroll
    for (int i = 0; i < 4; i++) {
        __nv_bfloat162 h = __floats2bfloat162_rn(f[2*i], f[2*i+1]);
        float r0 = f[2*i]     - __bfloat162float(h.x);
        float r1 = f[2*i + 1] - __bfloat162float(h.y);
        __nv_bfloat162 l = __floats2bfloat162_rn(r0, r1);
        hw[i] = *reinterpret_cast<uint32_t*>(&h);
        lw[i] = *reinterpret_cast<uint32_t*>(&l);
    }
    hi = make_uint4(hw[0], hw[1], hw[2], hw[3]);
    lo = make_uint4(lw[0], lw[1], lw[2], lw[3]);
}

// ---------------------------------------------------------------------------
// prep: p2, 1/var, zero accumulators, pre-split proto tiles
// grid 192 (m*64 + proto), 128 threads (8 cols each)
// ---------------------------------------------------------------------------
__global__ void prep_kernel(const float* __restrict__ pTF, const float* __restrict__ vTF,
                            const float* __restrict__ pDE, const float* __restrict__ vDE,
                            const float* __restrict__ pFFT, const float* __restrict__ vFFT)
{
    __shared__ float red[4];
    const int b = blockIdx.x;
    const int m = b >> 6, j = b & 63;
    const int tid = threadIdx.x;
    if (b == 0 && tid == 0) { g_loss_sum = 0.0f; g_acc_cnt = 0; }

    const float* P = (m == 0 ? pTF : (m == 1 ? pDE : pFFT)) + (size_t)j * DIMK;
    const int c0 = tid * 8;
    float4 x0 = *reinterpret_cast<const float4*>(P + c0);
    float4 x1 = *reinterpret_cast<const float4*>(P + c0 + 4);
    float s = x0.x*x0.x + x0.y*x0.y + x0.z*x0.z + x0.w*x0.w
            + x1.x*x1.x + x1.y*x1.y + x1.z*x1.z + x1.w*x1.w;

    uint4 hi, lo; split8(x0, x1, hi, lo);
    const int chunk = c0 >> 6;
    const int col   = c0 & 63;
    const size_t idx = (((size_t)(m * NCHUNK + chunk) * KCLS) + j) * KC + col;
    *reinterpret_cast<uint4*>(g_Bh + idx) = hi;
    *reinterpret_cast<uint4*>(g_Bl + idx) = lo;

    #pragma unroll
    for (int o = 16; o > 0; o >>= 1) s += __shfl_xor_sync(0xffffffffu, s, o);
    if ((tid & 31) == 0) red[tid >> 5] = s;
    __syncthreads();
    if (tid == 0) {
        g_p2[m][j] = red[0] + red[1] + red[2] + red[3];
        const float* V = (m == 0 ? vTF : (m == 1 ? vDE : vFFT));
        g_rvar[m][j] = 1.0f / V[j];
    }
}

// ---------------------------------------------------------------------------
// fused kernel: bf16 hi/lo-split HMMA GEMM + softmax + loss + argmax
// grid 256 CTAs x 256 threads; CTA = 32 rows of one class (cls = blockIdx.x>>2)
// ---------------------------------------------------------------------------
__global__ void __launch_bounds__(256, 2)
fusion_kernel(const float* __restrict__ xTF, const float* __restrict__ xDE,
              const float* __restrict__ xFFT)
{
    extern __shared__ unsigned char smemc[];
    const uint32_t sb = smem_u32(smemc);

    const int tid  = threadIdx.x;
    const int warp = tid >> 5;
    const int lane = tid & 31;
    const int lr   = tid >> 3;            // loader/softmax row (0..31)
    const int lc   = (tid & 7) * 8;       // loader/softmax col stripe base
    const int gr   = lane >> 2;
    const int lk   = (lane & 3) * 2;
    const int cls  = (int)(blockIdx.x >> 2);
    const size_t rowbase = (size_t)blockIdx.x * TMR;

    float* sL   = reinterpret_cast<float*>(smemc + OFF_SL);
    float* sX2  = reinterpret_cast<float*>(smemc + OFF_SX2);
    float* sP2  = reinterpret_cast<float*>(smemc + OFF_SP2);
    float* sRv  = reinterpret_cast<float*>(smemc + OFF_SRV);
    float* sBL  = reinterpret_cast<float*>(smemc + OFF_RED);
    int*   sBA  = reinterpret_cast<int*>(smemc + OFF_RED + 4);

    if (tid == 0) { *sBL = 0.0f; *sBA = 0; }

    // loop-invariant ldmatrix address parts (byte offsets within a buffer)
    const uint32_t aP = (uint32_t)(((lane & 15) * A_STR + (lane >> 4) * 8) * 2);
    const uint32_t bP = (uint32_t)((((warp * 8) + (lane & 7)) * A_STR + ((lane >> 3) & 1) * 8) * 2);
    // loader smem offsets
    const uint32_t aoff  = (uint32_t)((lr * A_STR + lc) * 2);
    const int j0 = tid * 2;
    const uint32_t boff0 = (uint32_t)((j0 >> 3) * (A_STR * 2) + (j0 & 7) * 16);
    const uint32_t boff1 = (uint32_t)(((j0 + 1) >> 3) * (A_STR * 2) + ((j0 + 1) & 7) * 16);

    const float* xs[3]  = {xTF, xDE, xFFT};
    const float  wts[3] = {1.0f, 0.8f, 0.6f};

    float pred[8];
    #pragma unroll
    for (int i = 0; i < 8; i++) pred[i] = 0.0f;
    float lossAcc = 0.0f;

    for (int m = 0; m < 3; m++) {
        if (tid < 64) { sP2[tid] = g_p2[m][tid]; sRv[tid] = g_rvar[m][tid]; }

        const float* aptr = xs[m] + (rowbase + lr) * DIMK + lc;
        const uint4* gBh = reinterpret_cast<const uint4*>(g_Bh) + (size_t)m * NCHUNK * 512;
        const uint4* gBl = reinterpret_cast<const uint4*>(g_Bl) + (size_t)m * NCHUNK * 512;

        float x2acc = 0.0f;
        float acc0[4] = {0,0,0,0}, acc1[4] = {0,0,0,0};

        // ---- chunk 0: load + split + store into buf0 ----
        {
            float4 a0 = *reinterpret_cast<const float4*>(aptr);
            float4 a1 = *reinterpret_cast<const float4*>(aptr + 4);
            uint4 bh0 = gBh[j0], bh1 = gBh[j0 + 1];
            uint4 bl0 = gBl[j0], bl1 = gBl[j0 + 1];
            uint4 hi, lo; split8(a0, a1, hi, lo);
            x2acc += a0.x*a0.x + a0.y*a0.y + a0.z*a0.z + a0.w*a0.w
                   + a1.x*a1.x + a1.y*a1.y + a1.z*a1.z + a1.w*a1.w;
            *reinterpret_cast<uint4*>(smemc + OFF_AH + aoff) = hi;
            *reinterpret_cast<uint4*>(smemc + OFF_AL + aoff) = lo;
            *reinterpret_cast<uint4*>(smemc + OFF_BH + boff0) = bh0;
            *reinterpret_cast<uint4*>(smemc + OFF_BH + boff1) = bh1;
            *reinterpret_cast<uint4*>(smemc + OFF_BL + boff0) = bl0;
            *reinterpret_cast<uint4*>(smemc + OFF_BL + boff1) = bl1;
        }
        __syncthreads();

        for (int ci = 0; ci < NCHUNK; ci++) {
            const uint32_t base = sb + (uint32_t)((ci & 1) * BUFSZ);
            const bool hasnext = (ci + 1 < NCHUNK);

            // prefetch next chunk into registers (LDG issued before MMA block)
            float4 na0, na1; uint4 nbh0, nbh1, nbl0, nbl1;
            if (hasnext) {
                const float* ap = aptr + (ci + 1) * KC;
                na0 = *reinterpret_cast<const float4*>(ap);
                na1 = *reinterpret_cast<const float4*>(ap + 4);
                const size_t bo = (size_t)(ci + 1) * 512;
                nbh0 = gBh[bo + j0]; nbh1 = gBh[bo + j0 + 1];
                nbl0 = gBl[bo + j0]; nbl1 = gBl[bo + j0 + 1];
            }

            // MMA on current buffer
            #pragma unroll
            for (int ks = 0; ks < 4; ks++) {
                uint32_t ah0[4], ah1[4], al0[4], al1[4], bhf[2], blf[2];
                const uint32_t ko = (uint32_t)(ks * 32);
                ldsm4(ah0, base + OFF_AH + aP + ko);
                ldsm4(ah1, base + OFF_AH + 2304 + aP + ko);
                ldsm4(al0, base + OFF_AL + aP + ko);
                ldsm4(al1, base + OFF_AL + 2304 + aP + ko);
                ldsm2(bhf, base + OFF_BH + bP + ko);
                ldsm2(blf, base + OFF_BL + bP + ko);
                mma_bf16(acc0, ah0, bhf);
                mma_bf16(acc0, ah0, blf);
                mma_bf16(acc0, al0, bhf);
                mma_bf16(acc1, ah1, bhf);
                mma_bf16(acc1, ah1, blf);
                mma_bf16(acc1, al1, bhf);
            }

            // split + store next chunk into other buffer
            if (hasnext) {
                const uint32_t nb = (uint32_t)(((ci + 1) & 1) * BUFSZ);
                uint4 hi, lo; split8(na0, na1, hi, lo);
                x2acc += na0.x*na0.x + na0.y*na0.y + na0.z*na0.z + na0.w*na0.w
                       + na1.x*na1.x + na1.y*na1.y + na1.z*na1.z + na1.w*na1.w;
                *reinterpret_cast<uint4*>(smemc + nb + OFF_AH + aoff) = hi;
                *reinterpret_cast<uint4*>(smemc + nb + OFF_AL + aoff) = lo;
                *reinterpret_cast<uint4*>(smemc + nb + OFF_BH + boff0) = nbh0;
                *reinterpret_cast<uint4*>(smemc + nb + OFF_BH + boff1) = nbh1;
                *reinterpret_cast<uint4*>(smemc + nb + OFF_BL + boff0) = nbl0;
                *reinterpret_cast<uint4*>(smemc + nb + OFF_BL + boff1) = nbl1;
            }
            __syncthreads();
        }

        // ---- epilogue: x2, logits transpose, softmax/loss/pred ----
        float x2t = x2acc;
        x2t += __shfl_xor_sync(0xffffffffu, x2t, 1);
        x2t += __shfl_xor_sync(0xffffffffu, x2t, 2);
        x2t += __shfl_xor_sync(0xffffffffu, x2t, 4);
        if ((tid & 7) == 0) sX2[lr] = x2t;
        __syncthreads();

        {
            const int c = warp * 8 + lk;
            const float p20 = sP2[c], p21 = sP2[c + 1];
            const float rv0 = sRv[c], rv1 = sRv[c + 1];
            #pragma unroll
            for (int mt = 0; mt < 2; mt++) {
                const float* A = mt ? acc1 : acc0;
                const int r0 = mt * 16 + gr;
                const float x2a = sX2[r0], x2b = sX2[r0 + 8];
                sL[r0 * SL_STR + c]           = fmaf(2.0f, A[0], -(x2a + p20)) * rv0;
                sL[r0 * SL_STR + c + 1]       = fmaf(2.0f, A[1], -(x2a + p21)) * rv1;
                sL[(r0 + 8) * SL_STR + c]     = fmaf(2.0f, A[2], -(x2b + p20)) * rv0;
                sL[(r0 + 8) * SL_STR + c + 1] = fmaf(2.0f, A[3], -(x2b + p21)) * rv1;
            }
        }
        __syncthreads();

        {
            const float* Lr = sL + lr * SL_STR;
            float f[8];
            #pragma unroll
            for (int i = 0; i < 8; i++) f[i] = Lr[lc + i];
            const float Ly = Lr[cls];

            float mx = f[0];
            #pragma unroll
            for (int i = 1; i < 8; i++) mx = fmaxf(mx, f[i]);
            mx = fmaxf(mx, __shfl_xor_sync(0xffffffffu, mx, 1));
            mx = fmaxf(mx, __shfl_xor_sync(0xffffffffu, mx, 2));
            mx = fmaxf(mx, __shfl_xor_sync(0xffffffffu, mx, 4));

            float s = 0.0f;
            #pragma unroll
            for (int i = 0; i < 8; i++) { f[i] = __expf(f[i] - mx); s += f[i]; }
            s += __shfl_xor_sync(0xffffffffu, s, 1);
            s += __shfl_xor_sync(0xffffffffu, s, 2);
            s += __shfl_xor_sync(0xffffffffu, s, 4);

            const float winv = wts[m] / s;
            #pragma unroll
            for (int i = 0; i < 8; i++) pred[i] += f[i] * winv;

            if ((tid & 7) == (cls >> 3))
                lossAcc += -wts[m] * (Ly - mx - logf(s));
        }
        __syncthreads();
    }

    // ---- final: argmax over fused preds (first-max tie-break) + reduction ----
    {
        float bv = pred[0]; int bi = lc;
        #pragma unroll
        for (int i = 1; i < 8; i++)
            if (pred[i] > bv) { bv = pred[i]; bi = lc + i; }
        #pragma unroll
        for (int o = 1; o <= 4; o <<= 1) {
            const float ov = __shfl_xor_sync(0xffffffffu, bv, o);
            const int   oi = __shfl_xor_sync(0xffffffffu, bi, o);
            if (ov > bv || (ov == bv && oi < bi)) { bv = ov; bi = oi; }
        }
        // row loss: sum the 8-lane group (exactly one lane holds nonzero)
        float ls = lossAcc;
        ls += __shfl_xor_sync(0xffffffffu, ls, 1);
        ls += __shfl_xor_sync(0xffffffffu, ls, 2);
        ls += __shfl_xor_sync(0xffffffffu, ls, 4);

        float lrow = ((lane & 7) == 0) ? ls : 0.0f;
        int   arow = ((lane & 7) == 0 && bi == cls) ? 1 : 0;
        lrow += __shfl_xor_sync(0xffffffffu, lrow, 8);
        lrow += __shfl_xor_sync(0xffffffffu, lrow, 16);
        arow += __shfl_xor_sync(0xffffffffu, arow, 8);
        arow += __shfl_xor_sync(0xffffffffu, arow, 16);
        if (lane == 0) {
            atomicAdd(sBL, lrow);
            atomicAdd(sBA, arow);
        }
    }
    __syncthreads();
    if (tid == 0) {
        atomicAdd(&g_loss_sum, *sBL);
        atomicAdd(&g_acc_cnt, *sBA);
    }
}

// ---------------------------------------------------------------------------
__global__ void finalize_kernel(float* __restrict__ out, int n)
{
    const float loss = g_loss_sum * (1.0f / NROWS);
    const float acc  = (float)g_acc_cnt * (1.0f / NROWS);
    for (int i = threadIdx.x; i < n; i += blockDim.x)
        out[i] = (i == 0) ? loss : (i == 1 ? acc : 0.0f);
}

// ---------------------------------------------------------------------------
extern "C" void kernel_launch(void* const* d_in, const int* in_sizes, int n_in,
                              void* d_out, int out_size)
{
    (void)in_sizes; (void)n_in;
    const float* TFq  = (const float*)d_in[0];
    const float* pTF  = (const float*)d_in[1];
    const float* vTF  = (const float*)d_in[2];
    const float* DEq  = (const float*)d_in[3];
    const float* pDE  = (const float*)d_in[4];
    const float* vDE  = (const float*)d_in[5];
    const float* FFTq = (const float*)d_in[6];
    const float* pFFT = (const float*)d_in[7];
    const float* vFFT = (const float*)d_in[8];

    static int smem_set = 0;
    if (!smem_set) {
        cudaFuncSetAttribute(fusion_kernel, cudaFuncAttributeMaxDynamicSharedMemorySize, SMEM_TOTAL);
        smem_set = 1;
    }

    prep_kernel<<<192, 128>>>(pTF, vTF, pDE, vDE, pFFT, vFFT);
    fusion_kernel<<<NCTA, 256, SMEM_TOTAL>>>(TFq, DEq, FFTq);
    finalize_kernel<<<1, 64>>>((float*)d_out, out_size);
}